// round 1
// baseline (speedup 1.0000x reference)
#include <cuda_runtime.h>

// IntensityTransformation: out_k[b,c,h,w] = tf_k[b,c, round(255*img[b,c,h,w])]
// img: [B,C,H,W] f32 (B=8,C=3,H=W=1024), tf1/2/3: [B,C,256] f32.
// Output: concat(out1,out2,out3) -> 3*B*C*H*W floats.
//
// Strategy: one CTA row (blockIdx.y) per (b,c) plane. Pack the three 256-entry
// LUTs into shared float4[256] so one LDS.128 serves all three gathers per
// pixel. Stream img/out as float4. Pure HBM-bound: ~403MB of traffic.

__global__ __launch_bounds__(256)
void intensity_lut_kernel(const float4* __restrict__ img,
                          const float*  __restrict__ tf1,
                          const float*  __restrict__ tf2,
                          const float*  __restrict__ tf3,
                          float4* __restrict__ out,
                          int hw4,          // H*W/4 per (b,c) plane
                          long long tot4)   // B*C*H*W/4 (stride between out1/out2/out3)
{
    __shared__ float4 lut[256];

    const int bc = blockIdx.y;
    const int t  = threadIdx.x;

    // Load the 3 LUTs for this (b,c): 256 entries each, packed as float4.
    if (t < 256) {
        const int base = bc * 256 + t;
        lut[t] = make_float4(tf1[base], tf2[base], tf3[base], 0.0f);
    }
    __syncthreads();

    long long i = (long long)blockIdx.x * blockDim.x + t;
    if (i >= hw4) return;

    const long long plane = (long long)bc * hw4;

    float4 v = img[plane + i];

    int i0 = __float2int_rn(255.0f * v.x);
    int i1 = __float2int_rn(255.0f * v.y);
    int i2 = __float2int_rn(255.0f * v.z);
    int i3 = __float2int_rn(255.0f * v.w);
    i0 = min(max(i0, 0), 255);
    i1 = min(max(i1, 0), 255);
    i2 = min(max(i2, 0), 255);
    i3 = min(max(i3, 0), 255);

    // One LDS.128 per pixel fetches (tf1,tf2,tf3) simultaneously.
    float4 l0 = lut[i0];
    float4 l1 = lut[i1];
    float4 l2 = lut[i2];
    float4 l3 = lut[i3];

    const long long o = plane + i;
    out[o]            = make_float4(l0.x, l1.x, l2.x, l3.x);  // tf1 output
    out[o + tot4]     = make_float4(l0.y, l1.y, l2.y, l3.y);  // tf2 output
    out[o + 2 * tot4] = make_float4(l0.z, l1.z, l2.z, l3.z);  // tf3 output
}

extern "C" void kernel_launch(void* const* d_in, const int* in_sizes, int n_in,
                              void* d_out, int out_size) {
    const float* img = (const float*)d_in[0];
    const float* tf1 = (const float*)d_in[1];
    const float* tf2 = (const float*)d_in[2];
    const float* tf3 = (const float*)d_in[3];
    float* out = (float*)d_out;

    const int n_img  = in_sizes[0];          // B*C*H*W
    const int n_lut  = in_sizes[1];          // B*C*256
    const int BC     = n_lut / 256;          // 24
    const int HW     = n_img / BC;           // 1048576
    const int hw4    = HW / 4;               // 262144
    const long long tot4 = (long long)n_img / 4;

    dim3 block(256);
    dim3 grid((hw4 + 255) / 256, BC);
    intensity_lut_kernel<<<grid, block>>>(
        (const float4*)img, tf1, tf2, tf3, (float4*)out, hw4, tot4);
}

// round 2
// speedup vs baseline: 1.0376x; 1.0376x over previous
#include <cuda_runtime.h>

// IntensityTransformation: out_k[b,c,h,w] = tf_k[b,c, round(255*img[b,c,h,w])]
// img: [B,C,H,W] f32 (B=8,C=3,H=W=1024), tf1/2/3: [B,C,256] f32.
// Output: concat(out1,out2,out3).
//
// R2: amortize the per-CTA LUT load over ITER=4 float4-iterations and
// front-batch the 4 independent global loads (MLP=4). 6144 CTAs total.

#define ITER 4

__global__ __launch_bounds__(256)
void intensity_lut_kernel(const float4* __restrict__ img,
                          const float*  __restrict__ tf1,
                          const float*  __restrict__ tf2,
                          const float*  __restrict__ tf3,
                          float4* __restrict__ out,
                          int hw4,          // H*W/4 per (b,c) plane
                          long long tot4)   // B*C*H*W/4 (stride between outputs)
{
    __shared__ float4 lut[256];

    const int bc = blockIdx.y;
    const int t  = threadIdx.x;

    // Load the 3 LUTs for this (b,c): packed as float4 so one LDS.128
    // serves all three gathers per pixel.
    if (t < 256) {
        const int base = bc * 256 + t;
        lut[t] = make_float4(tf1[base], tf2[base], tf3[base], 0.0f);
    }
    __syncthreads();

    const long long plane = (long long)bc * hw4;
    const long long chunk = (long long)blockIdx.x * (blockDim.x * ITER);

    // Front-batched loads: 4 independent LDG.128 in flight per thread.
    float4 v[ITER];
    long long idx[ITER];
#pragma unroll
    for (int k = 0; k < ITER; k++) {
        long long i = chunk + t + k * blockDim.x;
        idx[k] = (i < hw4) ? (plane + i) : plane;   // safe dummy
        v[k] = img[idx[k]];
    }

#pragma unroll
    for (int k = 0; k < ITER; k++) {
        long long i = chunk + t + k * blockDim.x;
        if (i >= hw4) continue;

        int i0 = __float2int_rn(255.0f * v[k].x);
        int i1 = __float2int_rn(255.0f * v[k].y);
        int i2 = __float2int_rn(255.0f * v[k].z);
        int i3 = __float2int_rn(255.0f * v[k].w);
        i0 = min(max(i0, 0), 255);
        i1 = min(max(i1, 0), 255);
        i2 = min(max(i2, 0), 255);
        i3 = min(max(i3, 0), 255);

        float4 l0 = lut[i0];
        float4 l1 = lut[i1];
        float4 l2 = lut[i2];
        float4 l3 = lut[i3];

        const long long o = plane + i;
        out[o]            = make_float4(l0.x, l1.x, l2.x, l3.x);
        out[o + tot4]     = make_float4(l0.y, l1.y, l2.y, l3.y);
        out[o + 2 * tot4] = make_float4(l0.z, l1.z, l2.z, l3.z);
    }
}

extern "C" void kernel_launch(void* const* d_in, const int* in_sizes, int n_in,
                              void* d_out, int out_size) {
    const float* img = (const float*)d_in[0];
    const float* tf1 = (const float*)d_in[1];
    const float* tf2 = (const float*)d_in[2];
    const float* tf3 = (const float*)d_in[3];
    float* out = (float*)d_out;

    const int n_img  = in_sizes[0];          // B*C*H*W
    const int n_lut  = in_sizes[1];          // B*C*256
    const int BC     = n_lut / 256;          // 24
    const int HW     = n_img / BC;           // 1048576
    const int hw4    = HW / 4;               // 262144
    const long long tot4 = (long long)n_img / 4;

    dim3 block(256);
    const int per_cta = 256 * ITER;
    dim3 grid((hw4 + per_cta - 1) / per_cta, BC);
    intensity_lut_kernel<<<grid, block>>>(
        (const float4*)img, tf1, tf2, tf3, (float4*)out, hw4, tot4);
}